// round 2
// baseline (speedup 1.0000x reference)
#include <cuda_runtime.h>
#include <math.h>

// ---------------- problem constants ----------------
// B=32, NS=NC=1024, D=256 (Dp=257), K=128 (Kp=129)

// ---------------- scratch layout (floats) ----------------
constexpr long long SZ_ABIG = 1024LL * 2048;          // [C1024 | -S1024]
constexpr long long SZ_C256 = 256LL * 256;
constexpr long long SZ_BND  = 32LL * 1024 * 256;
constexpr long long SZ_L    = 32LL * 1024 * 257;
constexpr long long SZ_LBIG = 32LL * 1024 * 1024;
constexpr long long SZ_H    = 32LL * 1024 * 128;
constexpr long long SZ_YBUF = 32LL * 2048 * 256;

constexpr long long OFF_ABIG = 0;
constexpr long long OFF_C256 = OFF_ABIG + SZ_ABIG;
constexpr long long OFF_S256 = OFF_C256 + SZ_C256;
constexpr long long OFF_YBUF = OFF_S256 + SZ_C256;
constexpr long long OFF_SFFT = OFF_YBUF + SZ_YBUF;
constexpr long long OFF_CFFT = OFF_SFFT + SZ_BND;
constexpr long long OFF_CLOG = OFF_CFFT + SZ_BND;
constexpr long long OFF_LS   = OFF_CLOG + SZ_BND;
constexpr long long OFF_LC   = OFF_LS + SZ_L;
constexpr long long OFF_LRAW = OFF_LC + SZ_L;
constexpr long long OFF_LFIX = OFF_LRAW + SZ_BND;
constexpr long long OFF_LBIG = OFF_LFIX + SZ_L;
constexpr long long OFF_XNL  = OFF_LBIG + SZ_LBIG;
constexpr long long OFF_XNC  = OFF_XNL + 32768;
constexpr long long OFF_HSA  = OFF_XNC + 32768;
constexpr long long OFF_HCA  = OFF_HSA + SZ_H;
constexpr long long OFF_MS   = OFF_HCA + SZ_H;
constexpr long long OFF_MC   = OFF_MS + SZ_H;
constexpr long long OFF_HCT  = OFF_MC + SZ_H;
constexpr long long OFF_LGS  = OFF_HCT + SZ_H;
constexpr long long OFF_LGC  = OFF_LGS + 32768;
constexpr long long TOTALF   = OFF_LGC + 32768;

__device__ float g_scratch[TOTALF];

// ---------------- device math helpers ----------------
__device__ __forceinline__ float artanh_clip(float x) {
    x = fminf(fmaxf(x, -1.f + 1e-5f), 1.f - 1e-5f);
    return 0.5f * (log1pf(x) - log1pf(-x));
}
__device__ __forceinline__ float gelu_exact(float x) {
    return 0.5f * x * (1.f + erff(x * 0.70710678118654752440f));
}

__device__ __forceinline__ float blockReduceSum(float v, float* sbuf) {
    int lane = threadIdx.x & 31, wid = threadIdx.x >> 5;
    #pragma unroll
    for (int o = 16; o; o >>= 1) v += __shfl_down_sync(0xffffffffu, v, o);
    if (lane == 0) sbuf[wid] = v;
    __syncthreads();
    int nw = (blockDim.x + 31) >> 5;
    float w = (threadIdx.x < nw) ? sbuf[threadIdx.x] : 0.f;
    if (wid == 0) {
        #pragma unroll
        for (int o = 16; o; o >>= 1) w += __shfl_down_sync(0xffffffffu, w, o);
        if (lane == 0) sbuf[32] = w;
    }
    __syncthreads();
    float r = sbuf[32];
    __syncthreads();
    return r;
}
__device__ __forceinline__ float blockReduceMax(float v, float* sbuf) {
    int lane = threadIdx.x & 31, wid = threadIdx.x >> 5;
    #pragma unroll
    for (int o = 16; o; o >>= 1) v = fmaxf(v, __shfl_down_sync(0xffffffffu, v, o));
    if (lane == 0) sbuf[wid] = v;
    __syncthreads();
    int nw = (blockDim.x + 31) >> 5;
    float w = (threadIdx.x < nw) ? sbuf[threadIdx.x] : -3.4e38f;
    if (wid == 0) {
        #pragma unroll
        for (int o = 16; o; o >>= 1) w = fmaxf(w, __shfl_down_sync(0xffffffffu, w, o));
        if (lane == 0) sbuf[32] = w;
    }
    __syncthreads();
    float r = sbuf[32];
    __syncthreads();
    return r;
}

// ---------------- generic batched SGEMM (fp32 SIMT, 128x128x8, 8x8/thread) ----------------
template <bool TA, bool TB>
__global__ void gemm_kernel(const float* __restrict__ A, const float* __restrict__ B,
                            float* __restrict__ C,
                            int M, int N, int K, int lda, int ldb, int ldc,
                            long long sA, long long sB, long long sC) {
    __shared__ float As[8][128];
    __shared__ float Bs[8][128];
    A += (long long)blockIdx.z * sA;
    B += (long long)blockIdx.z * sB;
    C += (long long)blockIdx.z * sC;
    int m0 = blockIdx.y * 128;
    int n0 = blockIdx.x * 128;
    int tid = threadIdx.x;
    int tx = tid & 15, ty = tid >> 4;

    float acc[8][8];
    #pragma unroll
    for (int i = 0; i < 8; i++)
        #pragma unroll
        for (int j = 0; j < 8; j++) acc[i][j] = 0.f;

    for (int k0 = 0; k0 < K; k0 += 8) {
        // load A tile: As[kk][mm] = A_eff[m0+mm, k0+kk]
        if (TA) {
            #pragma unroll
            for (int i = 0; i < 4; i++) {
                int idx = tid + i * 256;
                int mm = idx & 127, kk = idx >> 7;
                int m = m0 + mm, k = k0 + kk;
                As[kk][mm] = (m < M && k < K) ? A[(long long)k * lda + m] : 0.f;
            }
        } else {
            #pragma unroll
            for (int i = 0; i < 4; i++) {
                int idx = tid + i * 256;
                int kk = idx & 7, mm = idx >> 3;
                int m = m0 + mm, k = k0 + kk;
                As[kk][mm] = (m < M && k < K) ? A[(long long)m * lda + k] : 0.f;
            }
        }
        // load B tile: Bs[kk][nn] = B_eff[k0+kk, n0+nn]
        if (TB) {
            #pragma unroll
            for (int i = 0; i < 4; i++) {
                int idx = tid + i * 256;
                int kk = idx & 7, nn = idx >> 3;
                int n = n0 + nn, k = k0 + kk;
                Bs[kk][nn] = (n < N && k < K) ? B[(long long)n * ldb + k] : 0.f;
            }
        } else {
            #pragma unroll
            for (int i = 0; i < 4; i++) {
                int idx = tid + i * 256;
                int nn = idx & 127, kk = idx >> 7;
                int n = n0 + nn, k = k0 + kk;
                Bs[kk][nn] = (n < N && k < K) ? B[(long long)k * ldb + n] : 0.f;
            }
        }
        __syncthreads();
        #pragma unroll
        for (int kk = 0; kk < 8; kk++) {
            float4 a0 = *reinterpret_cast<const float4*>(&As[kk][ty * 8]);
            float4 a1 = *reinterpret_cast<const float4*>(&As[kk][ty * 8 + 4]);
            float4 b0 = *reinterpret_cast<const float4*>(&Bs[kk][tx * 8]);
            float4 b1 = *reinterpret_cast<const float4*>(&Bs[kk][tx * 8 + 4]);
            float ra[8] = {a0.x, a0.y, a0.z, a0.w, a1.x, a1.y, a1.z, a1.w};
            float rb[8] = {b0.x, b0.y, b0.z, b0.w, b1.x, b1.y, b1.z, b1.w};
            #pragma unroll
            for (int i = 0; i < 8; i++)
                #pragma unroll
                for (int j = 0; j < 8; j++) acc[i][j] += ra[i] * rb[j];
        }
        __syncthreads();
    }
    #pragma unroll
    for (int i = 0; i < 8; i++) {
        int m = m0 + ty * 8 + i;
        if (m >= M) continue;
        #pragma unroll
        for (int j = 0; j < 8; j++) {
            int n = n0 + tx * 8 + j;
            if (n < N) C[(long long)m * ldc + n] = acc[i][j];
        }
    }
}

// ---------------- small kernels ----------------
__global__ void k_twiddles(float* __restrict__ S) {
    long long i = (long long)blockIdx.x * blockDim.x + threadIdx.x;
    if (i < SZ_ABIG) {
        int k = (int)(i >> 11), n = (int)(i & 2047);
        int nn = (n < 1024) ? n : (n - 1024);
        int m = (k * nn) & 1023;
        float s, c;
        sincospif(2.f * (float)m / 1024.f, &s, &c);
        S[OFF_ABIG + i] = (n < 1024) ? c : -s;
    }
    if (i < 65536) {
        int r = (int)(i >> 8), cc = (int)(i & 255);
        int m = (r * cc) & 255;
        float s, c;
        sincospif(2.f * (float)m / 256.f, &s, &c);
        S[OFF_C256 + i] = c;
        S[OFF_S256 + i] = s;
    }
}

// p_logmap0 over rows of 256
__global__ void k_plogmap0(const float* __restrict__ in, float* __restrict__ out) {
    __shared__ float sred[33];
    long long row = blockIdx.x;
    int t = threadIdx.x;
    float x = in[row * 256 + t];
    float yn = sqrtf(fmaxf(blockReduceSum(x * x, sred), 1e-15f));
    out[row * 256 + t] = artanh_clip(yn) / yn * x;
}

// euclid_to_lorentz: rows 256 -> 257
__global__ void k_e2l(const float* __restrict__ in, float* __restrict__ out) {
    __shared__ float sred[33];
    long long row = blockIdx.x;
    int t = threadIdx.x;
    float x = in[row * 256 + t];
    float ssq = blockReduceSum(x * x, sred);
    float xn = sqrtf(fmaxf(ssq, 1e-15f)) + 1e-5f;
    float sc = fminf(1.f, 2.0f / xn);
    x *= sc;
    float vn = sqrtf(fmaxf(ssq * sc * sc, 1e-15f));
    out[row * 257 + 1 + t] = sinhf(vn) / vn * x;
    if (t == 0) out[row * 257] = coshf(vn);
}

// lorentz_linear fix: raw space (256) + bias -> [time, space] (257)
__global__ void k_lfix(const float* __restrict__ raw, const float* __restrict__ b,
                       float* __restrict__ out) {
    __shared__ float sred[33];
    long long row = blockIdx.x;
    int t = threadIdx.x;
    float sp = raw[row * 256 + t] + b[1 + t];
    float ssq = blockReduceSum(sp * sp, sred);
    out[row * 257 + 1 + t] = sp;
    if (t == 0) out[row * 257] = sqrtf(ssq + 1.f);
}

// lorentz_to_poincare(lorentz_linear): raw space (128) + bias -> space/(time+1), in place
__global__ void k_pfix(float* __restrict__ buf, const float* __restrict__ b) {
    __shared__ float sred[33];
    long long row = blockIdx.x;
    int t = threadIdx.x;
    float sp = buf[row * 128 + t] + b[1 + t];
    float ssq = blockReduceSum(sp * sp, sred);
    buf[row * 128 + t] = sp / (sqrtf(ssq + 1.f) + 1.f);
}

// lorentz_act on rows of 1024 (in place) + row norm xnl
__global__ void k_act(float* __restrict__ lbig, float* __restrict__ xnl) {
    __shared__ float sred[33];
    long long row = blockIdx.x;
    int t = threadIdx.x;
    float g[4];
    float ss = 0.f;
    #pragma unroll
    for (int j = 0; j < 4; j++) {
        int m = t + j * 256;
        float v = lbig[row * 1024 + m];
        float gg = gelu_exact(v);
        if (m == 0) gg = 0.f;
        g[j] = gg;
        ss += gg * gg;
    }
    float ssq = blockReduceSum(ss, sred);
    float time = sqrtf(1.f + ssq);
    #pragma unroll
    for (int j = 0; j < 4; j++) {
        int m = t + j * 256;
        lbig[row * 1024 + m] = (m == 0) ? time : g[j];
    }
    if (t == 0) xnl[row] = sqrtf(fmaxf(time * time + ssq, 1e-15f));
}

// column norms of L_act: xnc[b*1024+m]
__global__ void k_colnorm(const float* __restrict__ lbig, float* __restrict__ xnc) {
    int b = blockIdx.y;
    int m = blockIdx.x * 256 + threadIdx.x;
    const float* base = lbig + (long long)b * 1024 * 1024 + m;
    float ss = 0.f;
    for (int n = 0; n < 1024; n++) {
        float v = base[(long long)n * 1024];
        ss += v * v;
    }
    xnc[b * 1024 + m] = sqrtf(fmaxf(ss, 1e-15f));
}

// Hs pipeline: mobius_matvec factor, mobius_add, p_logmap0/gelu/p_expmap0, logits
__global__ void k_hs(float* __restrict__ ms, const float* __restrict__ hsa,
                     const float* __restrict__ xnl, const float* __restrict__ whs,
                     float* __restrict__ lgs) {
    __shared__ float sred[33];
    long long row = blockIdx.x;
    int t = threadIdx.x;
    float v = ms[row * 128 + t];
    float mxn = sqrtf(fmaxf(blockReduceSum(v * v, sred), 1e-15f));
    float xn = xnl[row];
    float fac = tanhf(mxn / xn * artanh_clip(xn)) / mxn;
    float y = fac * v;
    float x = hsa[row * 128 + t];
    float xy = blockReduceSum(x * y, sred);
    float x2 = blockReduceSum(x * x, sred);
    float y2 = blockReduceSum(y * y, sred);
    float den = fmaxf(1.f + 2.f * xy + x2 * y2, 1e-15f);
    float h = ((1.f + 2.f * xy + y2) * x + (1.f - x2) * y) / den;
    float hn = sqrtf(fmaxf(blockReduceSum(h * h, sred), 1e-15f));
    float u = artanh_clip(hn) / hn * h;
    float g = gelu_exact(u);
    float un = sqrtf(fmaxf(blockReduceSum(g * g, sred), 1e-15f));
    float o = tanhf(un) / un * g;
    ms[row * 128 + t] = o;
    float dot = blockReduceSum(o * whs[t], sred);
    float on2 = blockReduceSum(o * o, sred);
    if (t == 0) {
        float on = sqrtf(fmaxf(on2, 1e-15f));
        float mx1 = sqrtf(fmaxf(dot * dot, 1e-15f));
        lgs[row] = tanhf(mx1 / on * artanh_clip(on)) * (dot / mx1);
    }
}

// mobius_matvec factor for Hc_b (in place on mc)
__global__ void k_hcfac(float* __restrict__ mc, const float* __restrict__ xnc) {
    __shared__ float sred[33];
    long long row = blockIdx.x;
    int t = threadIdx.x;
    float v = mc[row * 128 + t];
    float mxn = sqrtf(fmaxf(blockReduceSum(v * v, sred), 1e-15f));
    float xn = xnc[row];
    float fac = tanhf(mxn / xn * artanh_clip(xn)) / mxn;
    mc[row * 128 + t] = fac * v;
}

// Hc pipeline over rows of 1024 (the m axis), writes Hc as (b,k,m)
__global__ void k_hc(const float* __restrict__ hca, const float* __restrict__ mc,
                     float* __restrict__ hct) {
    __shared__ float sred[33];
    int b = blockIdx.y, kq = blockIdx.x;
    int t = threadIdx.x;
    float x[4], y[4];
    #pragma unroll
    for (int j = 0; j < 4; j++) {
        int m = t + j * 256;
        long long idx = ((long long)b * 1024 + m) * 128 + kq;
        x[j] = hca[idx];
        y[j] = mc[idx];
    }
    float pxy = 0.f, px2 = 0.f, py2 = 0.f;
    #pragma unroll
    for (int j = 0; j < 4; j++) { pxy += x[j] * y[j]; px2 += x[j] * x[j]; py2 += y[j] * y[j]; }
    float xy = blockReduceSum(pxy, sred);
    float x2 = blockReduceSum(px2, sred);
    float y2 = blockReduceSum(py2, sred);
    float den = fmaxf(1.f + 2.f * xy + x2 * y2, 1e-15f);
    float h[4];
    float hs = 0.f;
    #pragma unroll
    for (int j = 0; j < 4; j++) {
        h[j] = ((1.f + 2.f * xy + y2) * x[j] + (1.f - x2) * y[j]) / den;
        hs += h[j] * h[j];
    }
    float hn = sqrtf(fmaxf(blockReduceSum(hs, sred), 1e-15f));
    float fa = artanh_clip(hn) / hn;
    float g[4];
    float gs = 0.f;
    #pragma unroll
    for (int j = 0; j < 4; j++) { g[j] = gelu_exact(fa * h[j]); gs += g[j] * g[j]; }
    float un = sqrtf(fmaxf(blockReduceSum(gs, sred), 1e-15f));
    float fb = tanhf(un) / un;
    #pragma unroll
    for (int j = 0; j < 4; j++) {
        int m = t + j * 256;
        hct[((long long)b * 128 + kq) * 1024 + m] = fb * g[j];
    }
}

// Ac logits: per (b,m), reduce over k of Hc[b,k,m]
__global__ void k_logc(const float* __restrict__ hct, const float* __restrict__ whc,
                       float* __restrict__ lgc) {
    int b = blockIdx.y;
    int m = blockIdx.x * 256 + threadIdx.x;
    const float* base = hct + (long long)b * 128 * 1024 + m;
    float ss = 0.f, dot = 0.f;
    #pragma unroll 4
    for (int k = 0; k < 128; k++) {
        float v = base[(long long)k * 1024];
        ss += v * v;
        dot += v * whc[k];
    }
    float xn = sqrtf(fmaxf(ss, 1e-15f));
    float mxn = sqrtf(fmaxf(dot * dot, 1e-15f));
    lgc[b * 1024 + m] = tanhf(mxn / xn * artanh_clip(xn)) * (dot / mxn);
}

__global__ void k_softmax(const float* __restrict__ in, float* __restrict__ out) {
    __shared__ float sred[33];
    int b = blockIdx.x, t = threadIdx.x;
    float v[4];
    float mx = -3.4e38f;
    #pragma unroll
    for (int j = 0; j < 4; j++) {
        v[j] = in[b * 1024 + t + j * 256];
        mx = fmaxf(mx, v[j]);
    }
    mx = blockReduceMax(mx, sred);
    float s = 0.f;
    #pragma unroll
    for (int j = 0; j < 4; j++) { v[j] = expf(v[j] - mx); s += v[j]; }
    s = blockReduceSum(s, sred);
    #pragma unroll
    for (int j = 0; j < 4; j++) out[b * 1024 + t + j * 256] = v[j] / s;
}

// centroid + lorentz_concat -> co_sc (32,513)
__global__ void k_final(const float* __restrict__ ls, const float* __restrict__ lc,
                        const float* __restrict__ as_, const float* __restrict__ ac_,
                        float* __restrict__ out) {
    __shared__ float sred[33];
    __shared__ float wsm[1024];
    __shared__ float avg[257];
    __shared__ float z[512];
    int b = blockIdx.x, t = threadIdx.x;

    // sentence centroid
    #pragma unroll
    for (int j = 0; j < 4; j++) wsm[t + j * 256] = as_[b * 1024 + t + j * 256];
    __syncthreads();
    float acc = 0.f, acc2 = 0.f;
    const float* lsb = ls + (long long)b * 1024 * 257;
    for (int n = 0; n < 1024; n++) {
        float w = wsm[n];
        acc += w * lsb[n * 257 + t];
        if (t == 0) acc2 += w * lsb[n * 257 + 256];
    }
    avg[t] = acc;
    if (t == 0) avg[256] = acc2;
    __syncthreads();
    float spsum = blockReduceSum(avg[1 + t] * avg[1 + t], sred);
    float a0 = avg[0];
    float den = sqrtf(fmaxf(fabsf(-a0 * a0 + spsum), 1e-8f));
    float cs = avg[1 + t] / den;
    float c0 = a0 / den;
    float spn = sqrtf(fmaxf(blockReduceSum(cs * cs, sred), 1e-15f));
    float tt = fmaxf(c0, 1.f + 1e-7f);
    z[t] = acoshf(tt) * cs / spn;
    __syncthreads();

    // comment centroid
    #pragma unroll
    for (int j = 0; j < 4; j++) wsm[t + j * 256] = ac_[b * 1024 + t + j * 256];
    __syncthreads();
    acc = 0.f; acc2 = 0.f;
    const float* lcb = lc + (long long)b * 1024 * 257;
    for (int n = 0; n < 1024; n++) {
        float w = wsm[n];
        acc += w * lcb[n * 257 + t];
        if (t == 0) acc2 += w * lcb[n * 257 + 256];
    }
    avg[t] = acc;
    if (t == 0) avg[256] = acc2;
    __syncthreads();
    spsum = blockReduceSum(avg[1 + t] * avg[1 + t], sred);
    a0 = avg[0];
    den = sqrtf(fmaxf(fabsf(-a0 * a0 + spsum), 1e-8f));
    cs = avg[1 + t] / den;
    c0 = a0 / den;
    spn = sqrtf(fmaxf(blockReduceSum(cs * cs, sred), 1e-15f));
    tt = fmaxf(c0, 1.f + 1e-7f);
    z[256 + t] = acoshf(tt) * cs / spn;
    __syncthreads();

    float zz = z[t] * z[t] + z[256 + t] * z[256 + t];
    float vn = sqrtf(fmaxf(blockReduceSum(zz, sred), 1e-15f));
    float f = sinhf(vn) / vn;
    float* ob = out + (long long)b * 513;
    if (t == 0) ob[0] = coshf(vn);
    ob[1 + t] = f * z[t];
    ob[257 + t] = f * z[256 + t];
}

// ---------------- host-side launch helpers ----------------
static void gemm(const float* A, const float* B, float* C, int M, int N, int K,
                 int lda, int ldb, int ldc, long long sA, long long sB, long long sC,
                 int batch, bool ta, bool tb) {
    dim3 grid((N + 127) / 128, (M + 127) / 128, batch);
    if (!ta && !tb) gemm_kernel<false, false><<<grid, 256>>>(A, B, C, M, N, K, lda, ldb, ldc, sA, sB, sC);
    else if (!ta && tb) gemm_kernel<false, true><<<grid, 256>>>(A, B, C, M, N, K, lda, ldb, ldc, sA, sB, sC);
    else if (ta && !tb) gemm_kernel<true, false><<<grid, 256>>>(A, B, C, M, N, K, lda, ldb, ldc, sA, sB, sC);
    else gemm_kernel<true, true><<<grid, 256>>>(A, B, C, M, N, K, lda, ldb, ldc, sA, sB, sC);
}

extern "C" void kernel_launch(void* const* d_in, const int* in_sizes, int n_in,
                              void* d_out, int out_size) {
    const float* sent = (const float*)d_in[0];
    const float* comm = (const float*)d_in[1];
    const float* WlW  = (const float*)d_in[2];
    const float* Wlb  = (const float*)d_in[3];
    const float* WcW  = (const float*)d_in[4];
    const float* Wcb  = (const float*)d_in[5];
    const float* WsW  = (const float*)d_in[6];
    const float* Wsb  = (const float*)d_in[7];
    const float* whs  = (const float*)d_in[8];
    const float* whc  = (const float*)d_in[9];
    float* out = (float*)d_out;

    float* S = nullptr;
    cudaGetSymbolAddress((void**)&S, g_scratch);

    float* abig = S + OFF_ABIG;
    float* c256 = S + OFF_C256;
    float* s256 = S + OFF_S256;
    float* ybuf = S + OFF_YBUF;
    float* sfft = S + OFF_SFFT;
    float* cfft = S + OFF_CFFT;
    float* clog = S + OFF_CLOG;
    float* Ls   = S + OFF_LS;
    float* Lc   = S + OFF_LC;
    float* lraw = S + OFF_LRAW;
    float* lfix = S + OFF_LFIX;
    float* lbig = S + OFF_LBIG;
    float* xnl  = S + OFF_XNL;
    float* xnc  = S + OFF_XNC;
    float* hsa  = S + OFF_HSA;
    float* hca  = S + OFF_HCA;
    float* ms   = S + OFF_MS;
    float* mc   = S + OFF_MC;
    float* hct  = S + OFF_HCT;
    float* lgs  = S + OFF_LGS;
    float* lgc  = S + OFF_LGC;

    float* out_co = out;                 // (32,513)
    float* out_as = out + 32 * 513;      // (32,1024)
    float* out_ac = out_as + 32 * 1024;  // (32,1024)

    // twiddles
    k_twiddles<<<(int)((SZ_ABIG + 255) / 256), 256>>>(S);

    // comment p_logmap0
    k_plogmap0<<<32 * 1024, 256>>>(comm, clog);

    // FFT (real part) for sentence: ybuf rows 0..1023=cos part, 1024..2047=sin part (per batch)
    gemm(sent, c256, ybuf,              1024, 256, 256,  256, 256, 256, 1024LL * 256, 0, 2048LL * 256, 32, false, false);
    gemm(sent, s256, ybuf + 1024 * 256, 1024, 256, 256,  256, 256, 256, 1024LL * 256, 0, 2048LL * 256, 32, false, false);
    gemm(abig, ybuf, sfft,              1024, 256, 2048, 2048, 256, 256, 0, 2048LL * 256, 1024LL * 256, 32, false, false);
    // FFT for comment (after logmap)
    gemm(clog, c256, ybuf,              1024, 256, 256,  256, 256, 256, 1024LL * 256, 0, 2048LL * 256, 32, false, false);
    gemm(clog, s256, ybuf + 1024 * 256, 1024, 256, 256,  256, 256, 256, 1024LL * 256, 0, 2048LL * 256, 32, false, false);
    gemm(abig, ybuf, cfft,              1024, 256, 2048, 2048, 256, 256, 0, 2048LL * 256, 1024LL * 256, 32, false, false);

    // euclid -> lorentz
    k_e2l<<<32 * 1024, 256>>>(sfft, Ls);
    k_e2l<<<32 * 1024, 256>>>(cfft, Lc);

    // lorentz_linear(Lc, Wl) -> lfix (space only GEMM, skip output row 0 of W)
    gemm(Lc, WlW + 257, lraw, 32 * 1024, 256, 257, 257, 257, 256, 0, 0, 0, 1, false, true);
    k_lfix<<<32 * 1024, 256>>>(lraw, Wlb, lfix);

    // einsum('bnd,bmd->bnm', Ls, lfix)
    gemm(Ls, lfix, lbig, 1024, 1024, 257, 257, 257, 1024, 1024LL * 257, 1024LL * 257, 1024LL * 1024, 32, false, true);
    k_act<<<32 * 1024, 256>>>(lbig, xnl);
    k_colnorm<<<dim3(4, 32), 256>>>(lbig, xnc);

    // Hs_a, Hc_a (poincare of lorentz_linear)
    gemm(Ls, WsW + 257, hsa, 32 * 1024, 128, 257, 257, 257, 128, 0, 0, 0, 1, false, true);
    k_pfix<<<32 * 1024, 128>>>(hsa, Wsb);
    gemm(Lc, WcW + 257, hca, 32 * 1024, 128, 257, 257, 257, 128, 0, 0, 0, 1, false, true);
    k_pfix<<<32 * 1024, 128>>>(hca, Wcb);

    // Hs path
    gemm(lbig, hca, ms, 1024, 128, 1024, 1024, 128, 128, 1024LL * 1024, 1024LL * 128, 1024LL * 128, 32, false, false);
    k_hs<<<32 * 1024, 128>>>(ms, hsa, xnl, whs, lgs);
    k_softmax<<<32, 256>>>(lgs, out_as);

    // Hc path
    gemm(lbig, hsa, mc, 1024, 128, 1024, 1024, 128, 128, 1024LL * 1024, 1024LL * 128, 1024LL * 128, 32, true, false);
    k_hcfac<<<32 * 1024, 128>>>(mc, xnc);
    k_hc<<<dim3(128, 32), 256>>>(hca, mc, hct);
    k_logc<<<dim3(4, 32), 256>>>(hct, whc, lgc);
    k_softmax<<<32, 256>>>(lgc, out_ac);

    // centroids + concat
    k_final<<<32, 256>>>(Ls, Lc, out_as, out_ac, out_co);

    (void)in_sizes; (void)n_in; (void)out_size;
}

// round 3
// speedup vs baseline: 1.2169x; 1.2169x over previous
#include <cuda_runtime.h>
#include <math.h>

// ---------------- problem constants ----------------
// B=32, NS=NC=1024, D=256 (Dp=257), K=128

// ---------------- scratch layout (floats) ----------------
constexpr long long SZ_CDH = 256LL * 129;
constexpr long long SZ_CH  = 513LL * 1024;
constexpr long long SZ_AB  = 32LL * 1024 * 129;
constexpr long long SZ_UV  = 32LL * 513 * 129;
constexpr long long SZ_BND = 32LL * 1024 * 256;
constexpr long long SZ_L   = 32LL * 1024 * 257;
constexpr long long SZ_LBIG= 32LL * 1024 * 1024;
constexpr long long SZ_H   = 32LL * 1024 * 128;

constexpr long long OFF_CDH  = 0;
constexpr long long OFF_SDH  = OFF_CDH + SZ_CDH;
constexpr long long OFF_CH   = OFF_SDH + SZ_CDH;
constexpr long long OFF_SH   = OFF_CH + SZ_CH;
constexpr long long OFF_ABUF = OFF_SH + SZ_CH;
constexpr long long OFF_BBUF = OFF_ABUF + SZ_AB;
constexpr long long OFF_U    = OFF_BBUF + SZ_AB;
constexpr long long OFF_V    = OFF_U + SZ_UV;
constexpr long long OFF_SFFT = OFF_V + SZ_UV;
constexpr long long OFF_CFFT = OFF_SFFT + SZ_BND;
constexpr long long OFF_CLOG = OFF_CFFT + SZ_BND;
constexpr long long OFF_LS   = OFF_CLOG + SZ_BND;
constexpr long long OFF_LC   = OFF_LS + SZ_L;
constexpr long long OFF_LRAW = OFF_LC + SZ_L;
constexpr long long OFF_LFIX = OFF_LRAW + SZ_BND;
constexpr long long OFF_LBIG = OFF_LFIX + SZ_L;
constexpr long long OFF_XNL  = OFF_LBIG + SZ_LBIG;
constexpr long long OFF_XNC  = OFF_XNL + 32768;
constexpr long long OFF_HSA  = OFF_XNC + 32768;
constexpr long long OFF_HCA  = OFF_HSA + SZ_H;
constexpr long long OFF_MS   = OFF_HCA + SZ_H;
constexpr long long OFF_MC   = OFF_MS + SZ_H;
constexpr long long OFF_HCT  = OFF_MC + SZ_H;
constexpr long long OFF_LGS  = OFF_HCT + SZ_H;
constexpr long long OFF_LGC  = OFF_LGS + 32768;
constexpr long long TOTALF   = OFF_LGC + 32768;

__device__ float g_scratch[TOTALF];

// ---------------- device math helpers ----------------
__device__ __forceinline__ float artanh_clip(float x) {
    x = fminf(fmaxf(x, -1.f + 1e-5f), 1.f - 1e-5f);
    return 0.5f * (log1pf(x) - log1pf(-x));
}
__device__ __forceinline__ float gelu_exact(float x) {
    return 0.5f * x * (1.f + erff(x * 0.70710678118654752440f));
}

__device__ __forceinline__ float blockReduceSum(float v, float* sbuf) {
    int lane = threadIdx.x & 31, wid = threadIdx.x >> 5;
    #pragma unroll
    for (int o = 16; o; o >>= 1) v += __shfl_down_sync(0xffffffffu, v, o);
    if (lane == 0) sbuf[wid] = v;
    __syncthreads();
    int nw = (blockDim.x + 31) >> 5;
    float w = (threadIdx.x < nw) ? sbuf[threadIdx.x] : 0.f;
    if (wid == 0) {
        #pragma unroll
        for (int o = 16; o; o >>= 1) w += __shfl_down_sync(0xffffffffu, w, o);
        if (lane == 0) sbuf[32] = w;
    }
    __syncthreads();
    float r = sbuf[32];
    __syncthreads();
    return r;
}
__device__ __forceinline__ float blockReduceMax(float v, float* sbuf) {
    int lane = threadIdx.x & 31, wid = threadIdx.x >> 5;
    #pragma unroll
    for (int o = 16; o; o >>= 1) v = fmaxf(v, __shfl_down_sync(0xffffffffu, v, o));
    if (lane == 0) sbuf[wid] = v;
    __syncthreads();
    int nw = (blockDim.x + 31) >> 5;
    float w = (threadIdx.x < nw) ? sbuf[threadIdx.x] : -3.4e38f;
    if (wid == 0) {
        #pragma unroll
        for (int o = 16; o; o >>= 1) w = fmaxf(w, __shfl_down_sync(0xffffffffu, w, o));
        if (lane == 0) sbuf[32] = w;
    }
    __syncthreads();
    float r = sbuf[32];
    __syncthreads();
    return r;
}

// ---------------- double-buffered batched SGEMM (fp32, 128x128x8, 8x8/thread) --------
template <bool TA, bool TB>
__global__ void __launch_bounds__(256) gemm_kernel(
        const float* __restrict__ A, const float* __restrict__ B,
        float* __restrict__ C,
        int M, int N, int K, int lda, int ldb, int ldc,
        long long sA, long long sB, long long sC) {
    __shared__ float As[2][8][128];
    __shared__ float Bs[2][8][128];
    A += (long long)blockIdx.z * sA;
    B += (long long)blockIdx.z * sB;
    C += (long long)blockIdx.z * sC;
    int m0 = blockIdx.y * 128;
    int n0 = blockIdx.x * 128;
    int tid = threadIdx.x;
    int tx = tid & 15, ty = tid >> 4;

    float acc[8][8];
    #pragma unroll
    for (int i = 0; i < 8; i++)
        #pragma unroll
        for (int j = 0; j < 8; j++) acc[i][j] = 0.f;

    float pa[4], pb[4];

    auto loadA = [&](int k0) {
        #pragma unroll
        for (int i = 0; i < 4; i++) {
            int idx = tid + i * 256;
            int mm, kk;
            if (TA) { mm = idx & 127; kk = idx >> 7; }
            else    { kk = idx & 7;   mm = idx >> 3; }
            int m = m0 + mm, k = k0 + kk;
            pa[i] = (m < M && k < K)
                      ? (TA ? A[(long long)k * lda + m] : A[(long long)m * lda + k])
                      : 0.f;
        }
    };
    auto stA = [&](int buf) {
        #pragma unroll
        for (int i = 0; i < 4; i++) {
            int idx = tid + i * 256;
            int mm, kk;
            if (TA) { mm = idx & 127; kk = idx >> 7; }
            else    { kk = idx & 7;   mm = idx >> 3; }
            As[buf][kk][mm] = pa[i];
        }
    };
    auto loadB = [&](int k0) {
        #pragma unroll
        for (int i = 0; i < 4; i++) {
            int idx = tid + i * 256;
            int nn, kk;
            if (TB) { kk = idx & 7;   nn = idx >> 3; }
            else    { nn = idx & 127; kk = idx >> 7; }
            int n = n0 + nn, k = k0 + kk;
            pb[i] = (n < N && k < K)
                      ? (TB ? B[(long long)n * ldb + k] : B[(long long)k * ldb + n])
                      : 0.f;
        }
    };
    auto stB = [&](int buf) {
        #pragma unroll
        for (int i = 0; i < 4; i++) {
            int idx = tid + i * 256;
            int nn, kk;
            if (TB) { kk = idx & 7;   nn = idx >> 3; }
            else    { nn = idx & 127; kk = idx >> 7; }
            Bs[buf][kk][nn] = pb[i];
        }
    };
    auto compute = [&](int buf) {
        #pragma unroll
        for (int kk = 0; kk < 8; kk++) {
            float4 a0 = *reinterpret_cast<const float4*>(&As[buf][kk][ty * 8]);
            float4 a1 = *reinterpret_cast<const float4*>(&As[buf][kk][ty * 8 + 4]);
            float4 b0 = *reinterpret_cast<const float4*>(&Bs[buf][kk][tx * 8]);
            float4 b1 = *reinterpret_cast<const float4*>(&Bs[buf][kk][tx * 8 + 4]);
            float ra[8] = {a0.x, a0.y, a0.z, a0.w, a1.x, a1.y, a1.z, a1.w};
            float rb[8] = {b0.x, b0.y, b0.z, b0.w, b1.x, b1.y, b1.z, b1.w};
            #pragma unroll
            for (int i = 0; i < 8; i++)
                #pragma unroll
                for (int j = 0; j < 8; j++) acc[i][j] += ra[i] * rb[j];
        }
    };

    loadA(0); loadB(0);
    stA(0); stB(0);
    __syncthreads();
    int buf = 0;
    for (int k0 = 8; k0 < K; k0 += 8) {
        loadA(k0); loadB(k0);      // prefetch (overlaps compute below)
        compute(buf);
        stA(buf ^ 1); stB(buf ^ 1);
        __syncthreads();
        buf ^= 1;
    }
    compute(buf);

    #pragma unroll
    for (int i = 0; i < 8; i++) {
        int m = m0 + ty * 8 + i;
        if (m >= M) continue;
        #pragma unroll
        for (int j = 0; j < 8; j++) {
            int n = n0 + tx * 8 + j;
            if (n < N) C[(long long)m * ldc + n] = acc[i][j];
        }
    }
}

// ---------------- small kernels ----------------
__global__ void k_twiddles(float* __restrict__ S) {
    long long i = (long long)blockIdx.x * blockDim.x + threadIdx.x;
    if (i < SZ_CDH) {
        int r = (int)(i / 129), j = (int)(i % 129);
        float s, c;
        sincospif(2.f * (float)((r * j) & 255) / 256.f, &s, &c);
        S[OFF_CDH + i] = c;
        S[OFF_SDH + i] = s;
    }
    if (i < SZ_CH) {
        int k = (int)(i >> 10), n = (int)(i & 1023);
        float s, c;
        sincospif(2.f * (float)((k * n) & 1023) / 1024.f, &s, &c);
        S[OFF_CH + i] = c;
        S[OFF_SH + i] = s;
    }
}

// scatter U,V into full Re(fft2) via 4-way symmetry
__global__ void k_fftcomb(const float* __restrict__ U, const float* __restrict__ V,
                          float* __restrict__ R) {
    int b = blockIdx.y;
    int i = blockIdx.x * 256 + threadIdx.x;
    if (i >= 513 * 129) return;
    int k = i / 129, j = i % 129;
    long long s = ((long long)b * 513 + k) * 129 + j;
    float u = U[s], v = V[s];
    float m = u - v, p = u + v;
    int k2 = (1024 - k) & 1023;
    int j2 = (256 - j) & 255;
    float* Rb = R + (long long)b * 1024 * 256;
    Rb[k * 256 + j] = m;
    if (k2 != k) Rb[k2 * 256 + j] = p;
    if (j2 != j) Rb[k * 256 + j2] = p;
    if (k2 != k && j2 != j) Rb[k2 * 256 + j2] = m;
}

// p_logmap0 over rows of 256
__global__ void k_plogmap0(const float* __restrict__ in, float* __restrict__ out) {
    __shared__ float sred[33];
    long long row = blockIdx.x;
    int t = threadIdx.x;
    float x = in[row * 256 + t];
    float yn = sqrtf(fmaxf(blockReduceSum(x * x, sred), 1e-15f));
    out[row * 256 + t] = artanh_clip(yn) / yn * x;
}

// euclid_to_lorentz: rows 256 -> 257
__global__ void k_e2l(const float* __restrict__ in, float* __restrict__ out) {
    __shared__ float sred[33];
    long long row = blockIdx.x;
    int t = threadIdx.x;
    float x = in[row * 256 + t];
    float ssq = blockReduceSum(x * x, sred);
    float xn = sqrtf(fmaxf(ssq, 1e-15f)) + 1e-5f;
    float sc = fminf(1.f, 2.0f / xn);
    x *= sc;
    float vn = sqrtf(fmaxf(ssq * sc * sc, 1e-15f));
    out[row * 257 + 1 + t] = sinhf(vn) / vn * x;
    if (t == 0) out[row * 257] = coshf(vn);
}

// lorentz_linear fix: raw space (256) + bias -> [time, space] (257)
__global__ void k_lfix(const float* __restrict__ raw, const float* __restrict__ b,
                       float* __restrict__ out) {
    __shared__ float sred[33];
    long long row = blockIdx.x;
    int t = threadIdx.x;
    float sp = raw[row * 256 + t] + b[1 + t];
    float ssq = blockReduceSum(sp * sp, sred);
    out[row * 257 + 1 + t] = sp;
    if (t == 0) out[row * 257] = sqrtf(ssq + 1.f);
}

// lorentz_to_poincare(lorentz_linear): raw space (128) + bias -> space/(time+1), in place
__global__ void k_pfix(float* __restrict__ buf, const float* __restrict__ b) {
    __shared__ float sred[33];
    long long row = blockIdx.x;
    int t = threadIdx.x;
    float sp = buf[row * 128 + t] + b[1 + t];
    float ssq = blockReduceSum(sp * sp, sred);
    buf[row * 128 + t] = sp / (sqrtf(ssq + 1.f) + 1.f);
}

// lorentz_act on rows of 1024 (in place) + row norm xnl
__global__ void k_act(float* __restrict__ lbig, float* __restrict__ xnl) {
    __shared__ float sred[33];
    long long row = blockIdx.x;
    int t = threadIdx.x;
    float g[4];
    float ss = 0.f;
    #pragma unroll
    for (int j = 0; j < 4; j++) {
        int m = t + j * 256;
        float v = lbig[row * 1024 + m];
        float gg = gelu_exact(v);
        if (m == 0) gg = 0.f;
        g[j] = gg;
        ss += gg * gg;
    }
    float ssq = blockReduceSum(ss, sred);
    float time = sqrtf(1.f + ssq);
    #pragma unroll
    for (int j = 0; j < 4; j++) {
        int m = t + j * 256;
        lbig[row * 1024 + m] = (m == 0) ? time : g[j];
    }
    if (t == 0) xnl[row] = sqrtf(fmaxf(time * time + ssq, 1e-15f));
}

// column norms of L_act: xnc[b*1024+m]
__global__ void k_colnorm(const float* __restrict__ lbig, float* __restrict__ xnc) {
    int b = blockIdx.y;
    int m = blockIdx.x * 256 + threadIdx.x;
    const float* base = lbig + (long long)b * 1024 * 1024 + m;
    float ss = 0.f;
    for (int n = 0; n < 1024; n++) {
        float v = base[(long long)n * 1024];
        ss += v * v;
    }
    xnc[b * 1024 + m] = sqrtf(fmaxf(ss, 1e-15f));
}

// Hs pipeline: mobius_matvec factor, mobius_add, p_logmap0/gelu/p_expmap0, logits
__global__ void k_hs(float* __restrict__ ms, const float* __restrict__ hsa,
                     const float* __restrict__ xnl, const float* __restrict__ whs,
                     float* __restrict__ lgs) {
    __shared__ float sred[33];
    long long row = blockIdx.x;
    int t = threadIdx.x;
    float v = ms[row * 128 + t];
    float mxn = sqrtf(fmaxf(blockReduceSum(v * v, sred), 1e-15f));
    float xn = xnl[row];
    float fac = tanhf(mxn / xn * artanh_clip(xn)) / mxn;
    float y = fac * v;
    float x = hsa[row * 128 + t];
    float xy = blockReduceSum(x * y, sred);
    float x2 = blockReduceSum(x * x, sred);
    float y2 = blockReduceSum(y * y, sred);
    float den = fmaxf(1.f + 2.f * xy + x2 * y2, 1e-15f);
    float h = ((1.f + 2.f * xy + y2) * x + (1.f - x2) * y) / den;
    float hn = sqrtf(fmaxf(blockReduceSum(h * h, sred), 1e-15f));
    float u = artanh_clip(hn) / hn * h;
    float g = gelu_exact(u);
    float un = sqrtf(fmaxf(blockReduceSum(g * g, sred), 1e-15f));
    float o = tanhf(un) / un * g;
    ms[row * 128 + t] = o;
    float dot = blockReduceSum(o * whs[t], sred);
    float on2 = blockReduceSum(o * o, sred);
    if (t == 0) {
        float on = sqrtf(fmaxf(on2, 1e-15f));
        float mx1 = sqrtf(fmaxf(dot * dot, 1e-15f));
        lgs[row] = tanhf(mx1 / on * artanh_clip(on)) * (dot / mx1);
    }
}

// mobius_matvec factor for Hc_b (in place on mc)
__global__ void k_hcfac(float* __restrict__ mc, const float* __restrict__ xnc) {
    __shared__ float sred[33];
    long long row = blockIdx.x;
    int t = threadIdx.x;
    float v = mc[row * 128 + t];
    float mxn = sqrtf(fmaxf(blockReduceSum(v * v, sred), 1e-15f));
    float xn = xnc[row];
    float fac = tanhf(mxn / xn * artanh_clip(xn)) / mxn;
    mc[row * 128 + t] = fac * v;
}

// Hc pipeline over rows of 1024 (the m axis), writes Hc as (b,k,m)
__global__ void k_hc(const float* __restrict__ hca, const float* __restrict__ mc,
                     float* __restrict__ hct) {
    __shared__ float sred[33];
    int b = blockIdx.y, kq = blockIdx.x;
    int t = threadIdx.x;
    float x[4], y[4];
    #pragma unroll
    for (int j = 0; j < 4; j++) {
        int m = t + j * 256;
        long long idx = ((long long)b * 1024 + m) * 128 + kq;
        x[j] = hca[idx];
        y[j] = mc[idx];
    }
    float pxy = 0.f, px2 = 0.f, py2 = 0.f;
    #pragma unroll
    for (int j = 0; j < 4; j++) { pxy += x[j] * y[j]; px2 += x[j] * x[j]; py2 += y[j] * y[j]; }
    float xy = blockReduceSum(pxy, sred);
    float x2 = blockReduceSum(px2, sred);
    float y2 = blockReduceSum(py2, sred);
    float den = fmaxf(1.f + 2.f * xy + x2 * y2, 1e-15f);
    float h[4];
    float hs = 0.f;
    #pragma unroll
    for (int j = 0; j < 4; j++) {
        h[j] = ((1.f + 2.f * xy + y2) * x[j] + (1.f - x2) * y[j]) / den;
        hs += h[j] * h[j];
    }
    float hn = sqrtf(fmaxf(blockReduceSum(hs, sred), 1e-15f));
    float fa = artanh_clip(hn) / hn;
    float g[4];
    float gs = 0.f;
    #pragma unroll
    for (int j = 0; j < 4; j++) { g[j] = gelu_exact(fa * h[j]); gs += g[j] * g[j]; }
    float un = sqrtf(fmaxf(blockReduceSum(gs, sred), 1e-15f));
    float fb = tanhf(un) / un;
    #pragma unroll
    for (int j = 0; j < 4; j++) {
        int m = t + j * 256;
        hct[((long long)b * 128 + kq) * 1024 + m] = fb * g[j];
    }
}

// Ac logits: per (b,m), reduce over k of Hc[b,k,m]
__global__ void k_logc(const float* __restrict__ hct, const float* __restrict__ whc,
                       float* __restrict__ lgc) {
    int b = blockIdx.y;
    int m = blockIdx.x * 256 + threadIdx.x;
    const float* base = hct + (long long)b * 128 * 1024 + m;
    float ss = 0.f, dot = 0.f;
    #pragma unroll 4
    for (int k = 0; k < 128; k++) {
        float v = base[(long long)k * 1024];
        ss += v * v;
        dot += v * whc[k];
    }
    float xn = sqrtf(fmaxf(ss, 1e-15f));
    float mxn = sqrtf(fmaxf(dot * dot, 1e-15f));
    lgc[b * 1024 + m] = tanhf(mxn / xn * artanh_clip(xn)) * (dot / mxn);
}

__global__ void k_softmax(const float* __restrict__ in, float* __restrict__ out) {
    __shared__ float sred[33];
    int b = blockIdx.x, t = threadIdx.x;
    float v[4];
    float mx = -3.4e38f;
    #pragma unroll
    for (int j = 0; j < 4; j++) {
        v[j] = in[b * 1024 + t + j * 256];
        mx = fmaxf(mx, v[j]);
    }
    mx = blockReduceMax(mx, sred);
    float s = 0.f;
    #pragma unroll
    for (int j = 0; j < 4; j++) { v[j] = expf(v[j] - mx); s += v[j]; }
    s = blockReduceSum(s, sred);
    #pragma unroll
    for (int j = 0; j < 4; j++) out[b * 1024 + t + j * 256] = v[j] / s;
}

// centroid + lorentz_concat -> co_sc (32,513)
__global__ void k_final(const float* __restrict__ ls, const float* __restrict__ lc,
                        const float* __restrict__ as_, const float* __restrict__ ac_,
                        float* __restrict__ out) {
    __shared__ float sred[33];
    __shared__ float wsm[1024];
    __shared__ float avg[257];
    __shared__ float z[512];
    int b = blockIdx.x, t = threadIdx.x;

    // sentence centroid
    #pragma unroll
    for (int j = 0; j < 4; j++) wsm[t + j * 256] = as_[b * 1024 + t + j * 256];
    __syncthreads();
    float acc = 0.f, acc2 = 0.f;
    const float* lsb = ls + (long long)b * 1024 * 257;
    for (int n = 0; n < 1024; n++) {
        float w = wsm[n];
        acc += w * lsb[n * 257 + t];
        if (t == 0) acc2 += w * lsb[n * 257 + 256];
    }
    avg[t] = acc;
    if (t == 0) avg[256] = acc2;
    __syncthreads();
    float spsum = blockReduceSum(avg[1 + t] * avg[1 + t], sred);
    float a0 = avg[0];
    float den = sqrtf(fmaxf(fabsf(-a0 * a0 + spsum), 1e-8f));
    float cs = avg[1 + t] / den;
    float c0 = a0 / den;
    float spn = sqrtf(fmaxf(blockReduceSum(cs * cs, sred), 1e-15f));
    float tt = fmaxf(c0, 1.f + 1e-7f);
    z[t] = acoshf(tt) * cs / spn;
    __syncthreads();

    // comment centroid
    #pragma unroll
    for (int j = 0; j < 4; j++) wsm[t + j * 256] = ac_[b * 1024 + t + j * 256];
    __syncthreads();
    acc = 0.f; acc2 = 0.f;
    const float* lcb = lc + (long long)b * 1024 * 257;
    for (int n = 0; n < 1024; n++) {
        float w = wsm[n];
        acc += w * lcb[n * 257 + t];
        if (t == 0) acc2 += w * lcb[n * 257 + 256];
    }
    avg[t] = acc;
    if (t == 0) avg[256] = acc2;
    __syncthreads();
    spsum = blockReduceSum(avg[1 + t] * avg[1 + t], sred);
    a0 = avg[0];
    den = sqrtf(fmaxf(fabsf(-a0 * a0 + spsum), 1e-8f));
    cs = avg[1 + t] / den;
    c0 = a0 / den;
    spn = sqrtf(fmaxf(blockReduceSum(cs * cs, sred), 1e-15f));
    tt = fmaxf(c0, 1.f + 1e-7f);
    z[256 + t] = acoshf(tt) * cs / spn;
    __syncthreads();

    float zz = z[t] * z[t] + z[256 + t] * z[256 + t];
    float vn = sqrtf(fmaxf(blockReduceSum(zz, sred), 1e-15f));
    float f = sinhf(vn) / vn;
    float* ob = out + (long long)b * 513;
    if (t == 0) ob[0] = coshf(vn);
    ob[1 + t] = f * z[t];
    ob[257 + t] = f * z[256 + t];
}

// ---------------- host-side launch helpers ----------------
static void gemm(const float* A, const float* B, float* C, int M, int N, int K,
                 int lda, int ldb, int ldc, long long sA, long long sB, long long sC,
                 int batch, bool ta, bool tb) {
    dim3 grid((N + 127) / 128, (M + 127) / 128, batch);
    if (!ta && !tb) gemm_kernel<false, false><<<grid, 256>>>(A, B, C, M, N, K, lda, ldb, ldc, sA, sB, sC);
    else if (!ta && tb) gemm_kernel<false, true><<<grid, 256>>>(A, B, C, M, N, K, lda, ldb, ldc, sA, sB, sC);
    else if (ta && !tb) gemm_kernel<true, false><<<grid, 256>>>(A, B, C, M, N, K, lda, ldb, ldc, sA, sB, sC);
    else gemm_kernel<true, true><<<grid, 256>>>(A, B, C, M, N, K, lda, ldb, ldc, sA, sB, sC);
}

extern "C" void kernel_launch(void* const* d_in, const int* in_sizes, int n_in,
                              void* d_out, int out_size) {
    const float* sent = (const float*)d_in[0];
    const float* comm = (const float*)d_in[1];
    const float* WlW  = (const float*)d_in[2];
    const float* Wlb  = (const float*)d_in[3];
    const float* WcW  = (const float*)d_in[4];
    const float* Wcb  = (const float*)d_in[5];
    const float* WsW  = (const float*)d_in[6];
    const float* Wsb  = (const float*)d_in[7];
    const float* whs  = (const float*)d_in[8];
    const float* whc  = (const float*)d_in[9];
    float* out = (float*)d_out;

    float* S = nullptr;
    cudaGetSymbolAddress((void**)&S, g_scratch);

    float* cdh  = S + OFF_CDH;
    float* sdh  = S + OFF_SDH;
    float* ch   = S + OFF_CH;
    float* sh   = S + OFF_SH;
    float* abuf = S + OFF_ABUF;
    float* bbuf = S + OFF_BBUF;
    float* ubuf = S + OFF_U;
    float* vbuf = S + OFF_V;
    float* sfft = S + OFF_SFFT;
    float* cfft = S + OFF_CFFT;
    float* clog = S + OFF_CLOG;
    float* Ls   = S + OFF_LS;
    float* Lc   = S + OFF_LC;
    float* lraw = S + OFF_LRAW;
    float* lfix = S + OFF_LFIX;
    float* lbig = S + OFF_LBIG;
    float* xnl  = S + OFF_XNL;
    float* xnc  = S + OFF_XNC;
    float* hsa  = S + OFF_HSA;
    float* hca  = S + OFF_HCA;
    float* ms   = S + OFF_MS;
    float* mc   = S + OFF_MC;
    float* hct  = S + OFF_HCT;
    float* lgs  = S + OFF_LGS;
    float* lgc  = S + OFF_LGC;

    float* out_co = out;                 // (32,513)
    float* out_as = out + 32 * 513;      // (32,1024)
    float* out_ac = out_as + 32 * 1024;  // (32,1024)

    // twiddles
    k_twiddles<<<(int)((SZ_CH + 255) / 256), 256>>>(S);

    // comment p_logmap0
    k_plogmap0<<<32 * 1024, 256>>>(comm, clog);

    // ---- FFT (real part) via 4-way symmetry ----
    // sentence
    gemm(sent, cdh, abuf, 1024, 129, 256, 256, 129, 129, 1024LL * 256, 0, 1024LL * 129, 32, false, false);
    gemm(sent, sdh, bbuf, 1024, 129, 256, 256, 129, 129, 1024LL * 256, 0, 1024LL * 129, 32, false, false);
    gemm(ch, abuf, ubuf, 513, 129, 1024, 1024, 129, 129, 0, 1024LL * 129, 513LL * 129, 32, false, false);
    gemm(sh, bbuf, vbuf, 513, 129, 1024, 1024, 129, 129, 0, 1024LL * 129, 513LL * 129, 32, false, false);
    k_fftcomb<<<dim3((513 * 129 + 255) / 256, 32), 256>>>(ubuf, vbuf, sfft);
    // comment (after logmap)
    gemm(clog, cdh, abuf, 1024, 129, 256, 256, 129, 129, 1024LL * 256, 0, 1024LL * 129, 32, false, false);
    gemm(clog, sdh, bbuf, 1024, 129, 256, 256, 129, 129, 1024LL * 256, 0, 1024LL * 129, 32, false, false);
    gemm(ch, abuf, ubuf, 513, 129, 1024, 1024, 129, 129, 0, 1024LL * 129, 513LL * 129, 32, false, false);
    gemm(sh, bbuf, vbuf, 513, 129, 1024, 1024, 129, 129, 0, 1024LL * 129, 513LL * 129, 32, false, false);
    k_fftcomb<<<dim3((513 * 129 + 255) / 256, 32), 256>>>(ubuf, vbuf, cfft);

    // euclid -> lorentz
    k_e2l<<<32 * 1024, 256>>>(sfft, Ls);
    k_e2l<<<32 * 1024, 256>>>(cfft, Lc);

    // lorentz_linear(Lc, Wl) -> lfix (space only GEMM, skip output row 0 of W)
    gemm(Lc, WlW + 257, lraw, 32 * 1024, 256, 257, 257, 257, 256, 0, 0, 0, 1, false, true);
    k_lfix<<<32 * 1024, 256>>>(lraw, Wlb, lfix);

    // einsum('bnd,bmd->bnm', Ls, lfix)
    gemm(Ls, lfix, lbig, 1024, 1024, 257, 257, 257, 1024, 1024LL * 257, 1024LL * 257, 1024LL * 1024, 32, false, true);
    k_act<<<32 * 1024, 256>>>(lbig, xnl);
    k_colnorm<<<dim3(4, 32), 256>>>(lbig, xnc);

    // Hs_a, Hc_a (poincare of lorentz_linear)
    gemm(Ls, WsW + 257, hsa, 32 * 1024, 128, 257, 257, 257, 128, 0, 0, 0, 1, false, true);
    k_pfix<<<32 * 1024, 128>>>(hsa, Wsb);
    gemm(Lc, WcW + 257, hca, 32 * 1024, 128, 257, 257, 257, 128, 0, 0, 0, 1, false, true);
    k_pfix<<<32 * 1024, 128>>>(hca, Wcb);

    // Hs path
    gemm(lbig, hca, ms, 1024, 128, 1024, 1024, 128, 128, 1024LL * 1024, 1024LL * 128, 1024LL * 128, 32, false, false);
    k_hs<<<32 * 1024, 128>>>(ms, hsa, xnl, whs, lgs);
    k_softmax<<<32, 256>>>(lgs, out_as);

    // Hc path
    gemm(lbig, hsa, mc, 1024, 128, 1024, 1024, 128, 128, 1024LL * 1024, 1024LL * 128, 1024LL * 128, 32, true, false);
    k_hcfac<<<32 * 1024, 128>>>(mc, xnc);
    k_hc<<<dim3(128, 32), 256>>>(hca, mc, hct);
    k_logc<<<dim3(4, 32), 256>>>(hct, whc, lgc);
    k_softmax<<<32, 256>>>(lgc, out_ac);

    // centroids + concat
    k_final<<<32, 256>>>(Ls, Lc, out_as, out_ac, out_co);

    (void)in_sizes; (void)n_in; (void)out_size;
}

// round 4
// speedup vs baseline: 2.2200x; 1.8243x over previous
#include <cuda_runtime.h>
#include <math.h>

// ---------------- problem constants ----------------
// B=32, NS=NC=1024, D=256 (Dp=257), K=128

// ---------------- scratch layout (floats) ----------------
constexpr long long SZ_Y    = 32LL * 129 * 1024;   // one complex plane
constexpr long long SZ_ZF   = 32LL * 256 * 1024;
constexpr long long SZ_BND  = 32LL * 1024 * 256;
constexpr long long SZ_L    = 32LL * 1024 * 257;
constexpr long long SZ_LBIG = 32LL * 1024 * 1024;
constexpr long long SZ_H    = 32LL * 1024 * 128;

constexpr long long OFF_YRE  = 0;
constexpr long long OFF_YIM  = OFF_YRE + SZ_Y;
constexpr long long OFF_ZF   = OFF_YIM + SZ_Y;
constexpr long long OFF_SFFT = OFF_ZF + SZ_ZF;
constexpr long long OFF_CFFT = OFF_SFFT + SZ_BND;
constexpr long long OFF_LS   = OFF_CFFT + SZ_BND;
constexpr long long OFF_LC   = OFF_LS + SZ_L;
constexpr long long OFF_LRAW = OFF_LC + SZ_L;
constexpr long long OFF_LFIX = OFF_LRAW + SZ_BND;
constexpr long long OFF_LBIG = OFF_LFIX + SZ_L;
constexpr long long OFF_XNL  = OFF_LBIG + SZ_LBIG;
constexpr long long OFF_XNC  = OFF_XNL + 32768;
constexpr long long OFF_HSA  = OFF_XNC + 32768;
constexpr long long OFF_HCA  = OFF_HSA + SZ_H;
constexpr long long OFF_MS   = OFF_HCA + SZ_H;
constexpr long long OFF_MC   = OFF_MS + SZ_H;
constexpr long long OFF_HCT  = OFF_MC + SZ_H;
constexpr long long OFF_LGS  = OFF_HCT + SZ_H;
constexpr long long OFF_LGC  = OFF_LGS + 32768;
constexpr long long TOTALF   = OFF_LGC + 32768;

__device__ float g_scratch[TOTALF];

// ---------------- device math helpers ----------------
__device__ __forceinline__ float artanh_clip(float x) {
    x = fminf(fmaxf(x, -1.f + 1e-5f), 1.f - 1e-5f);
    return 0.5f * (log1pf(x) - log1pf(-x));
}
__device__ __forceinline__ float gelu_exact(float x) {
    return 0.5f * x * (1.f + erff(x * 0.70710678118654752440f));
}

__device__ __forceinline__ float blockReduceSum(float v, float* sbuf) {
    int lane = threadIdx.x & 31, wid = threadIdx.x >> 5;
    #pragma unroll
    for (int o = 16; o; o >>= 1) v += __shfl_down_sync(0xffffffffu, v, o);
    if (lane == 0) sbuf[wid] = v;
    __syncthreads();
    int nw = (blockDim.x + 31) >> 5;
    float w = (threadIdx.x < nw) ? sbuf[threadIdx.x] : 0.f;
    if (wid == 0) {
        #pragma unroll
        for (int o = 16; o; o >>= 1) w += __shfl_down_sync(0xffffffffu, w, o);
        if (lane == 0) sbuf[32] = w;
    }
    __syncthreads();
    float r = sbuf[32];
    __syncthreads();
    return r;
}
// fused 3-way sum reduction (saves barrier rounds)
__device__ __forceinline__ void blockReduceSum3(float& a, float& b, float& c, float* sbuf) {
    int lane = threadIdx.x & 31, wid = threadIdx.x >> 5;
    #pragma unroll
    for (int o = 16; o; o >>= 1) {
        a += __shfl_down_sync(0xffffffffu, a, o);
        b += __shfl_down_sync(0xffffffffu, b, o);
        c += __shfl_down_sync(0xffffffffu, c, o);
    }
    if (lane == 0) { sbuf[wid] = a; sbuf[34 + wid] = b; sbuf[68 + wid] = c; }
    __syncthreads();
    int nw = (blockDim.x + 31) >> 5;
    float ra = (threadIdx.x < nw) ? sbuf[threadIdx.x] : 0.f;
    float rb = (threadIdx.x < nw) ? sbuf[34 + threadIdx.x] : 0.f;
    float rc = (threadIdx.x < nw) ? sbuf[68 + threadIdx.x] : 0.f;
    if (wid == 0) {
        #pragma unroll
        for (int o = 16; o; o >>= 1) {
            ra += __shfl_down_sync(0xffffffffu, ra, o);
            rb += __shfl_down_sync(0xffffffffu, rb, o);
            rc += __shfl_down_sync(0xffffffffu, rc, o);
        }
        if (lane == 0) { sbuf[33] = ra; sbuf[67] = rb; sbuf[101] = rc; }
    }
    __syncthreads();
    a = sbuf[33]; b = sbuf[67]; c = sbuf[101];
    __syncthreads();
}
__device__ __forceinline__ float blockReduceMax(float v, float* sbuf) {
    int lane = threadIdx.x & 31, wid = threadIdx.x >> 5;
    #pragma unroll
    for (int o = 16; o; o >>= 1) v = fmaxf(v, __shfl_down_sync(0xffffffffu, v, o));
    if (lane == 0) sbuf[wid] = v;
    __syncthreads();
    int nw = (blockDim.x + 31) >> 5;
    float w = (threadIdx.x < nw) ? sbuf[threadIdx.x] : -3.4e38f;
    if (wid == 0) {
        #pragma unroll
        for (int o = 16; o; o >>= 1) w = fmaxf(w, __shfl_down_sync(0xffffffffu, w, o));
        if (lane == 0) sbuf[32] = w;
    }
    __syncthreads();
    float r = sbuf[32];
    __syncthreads();
    return r;
}

// ---------------- FFT kernels (Stockham radix-2, DIF, autosort) ----------------
// Row FFT: 256-point complex FFT of each real row of 256; keep bins 0..128.
// Output layout: yre/yim[(b*129 + j)*1024 + n]
template <bool LOGMAP>
__global__ void f_row256(const float* __restrict__ in,
                         float* __restrict__ yre, float* __restrict__ yim) {
    __shared__ float re[2][256], im[2][256], sred[34];
    long long row = blockIdx.x;      // b*1024 + n
    int t = threadIdx.x;             // 0..127
    float x0 = in[row * 256 + t];
    float x1 = in[row * 256 + t + 128];
    if (LOGMAP) {
        float ssq = blockReduceSum(x0 * x0 + x1 * x1, sred);
        float yn = sqrtf(fmaxf(ssq, 1e-15f));
        float f = artanh_clip(yn) / yn;
        x0 *= f; x1 *= f;
    }
    re[0][t] = x0; re[0][t + 128] = x1;
    im[0][t] = 0.f; im[0][t + 128] = 0.f;
    __syncthreads();
    int src = 0;
    #pragma unroll
    for (int s = 0; s < 8; s++) {
        int m = 1 << s, l = 128 >> s;
        int j = t >> s, k = t & (m - 1);
        float a = (float)j / (float)l, sn, cs;
        sincospif(a, &sn, &cs);      // w = cs - i*sn
        int i0 = k + j * m, i1 = i0 + l * m;
        int d0 = k + 2 * j * m, d1 = d0 + m;
        float are = re[src][i0], aim = im[src][i0];
        float bre = re[src][i1], bim = im[src][i1];
        re[src ^ 1][d0] = are + bre; im[src ^ 1][d0] = aim + bim;
        float tre = are - bre, tim = aim - bim;
        re[src ^ 1][d1] = cs * tre + sn * tim;
        im[src ^ 1][d1] = cs * tim - sn * tre;
        src ^= 1;
        __syncthreads();
    }
    int b = (int)(row >> 10), n = (int)(row & 1023);
    long long ob = ((long long)b * 129) * 1024 + n;
    yre[ob + (long long)t * 1024] = re[src][t];
    yim[ob + (long long)t * 1024] = im[src][t];
    if (t == 0) {
        yre[ob + 128LL * 1024] = re[src][128];
        yim[ob + 128LL * 1024] = im[src][128];
    }
}

// Column FFT: 1024-point complex FFT along n for each (b,j); keep Re only.
// Output: zf[(b*256 + j)*1024 + k]
__global__ void __launch_bounds__(512) f_col1024(
        const float* __restrict__ yre, const float* __restrict__ yim,
        float* __restrict__ zf) {
    __shared__ float re[2][1024], im[2][1024];
    int j = blockIdx.x, b = blockIdx.y, t = threadIdx.x;  // 512 threads
    long long ib = ((long long)b * 129 + j) * 1024;
    re[0][t] = yre[ib + t]; re[0][t + 512] = yre[ib + t + 512];
    im[0][t] = yim[ib + t]; im[0][t + 512] = yim[ib + t + 512];
    __syncthreads();
    int src = 0;
    #pragma unroll
    for (int s = 0; s < 10; s++) {
        int m = 1 << s, l = 512 >> s;
        int jj = t >> s, k = t & (m - 1);
        float a = (float)jj / (float)l, sn, cs;
        sincospif(a, &sn, &cs);
        int i0 = k + jj * m, i1 = i0 + l * m;
        int d0 = k + 2 * jj * m, d1 = d0 + m;
        float are = re[src][i0], aim = im[src][i0];
        float bre = re[src][i1], bim = im[src][i1];
        re[src ^ 1][d0] = are + bre; im[src ^ 1][d0] = aim + bim;
        float tre = are - bre, tim = aim - bim;
        re[src ^ 1][d1] = cs * tre + sn * tim;
        im[src ^ 1][d1] = cs * tim - sn * tre;
        src ^= 1;
        __syncthreads();
    }
    long long ob = ((long long)b * 256 + j) * 1024;
    zf[ob + t] = re[src][t];
    zf[ob + t + 512] = re[src][t + 512];
}

// Mirror fill: Re Z[k, j'] = Re Z[(1024-k)%1024, 256-j'] for j'=129..255
__global__ void f_mirror(float* __restrict__ zf) {
    int jp = 129 + blockIdx.x;   // 129..255
    int b = blockIdx.y;
    long long dst = ((long long)b * 256 + jp) * 1024;
    long long srcr = ((long long)b * 256 + (256 - jp)) * 1024;
    for (int k = threadIdx.x; k < 1024; k += 256) {
        int ks = (1024 - k) & 1023;
        zf[dst + k] = zf[srcr + ks];
    }
}

// Transpose zf[b][j][k] (256x1024) -> R[b][k][j] (1024x256)
__global__ void f_transpose(const float* __restrict__ zf, float* __restrict__ R) {
    __shared__ float tile[32][33];
    int k0 = blockIdx.x * 32, j0 = blockIdx.y * 32, b = blockIdx.z;
    for (int r = threadIdx.y; r < 32; r += 8)
        tile[r][threadIdx.x] = zf[((long long)b * 256 + j0 + r) * 1024 + k0 + threadIdx.x];
    __syncthreads();
    for (int r = threadIdx.y; r < 32; r += 8)
        R[((long long)b * 1024 + k0 + r) * 256 + j0 + threadIdx.x] = tile[threadIdx.x][r];
}

// ---------------- double-buffered batched SGEMM (fp32, 128x128x8, 8x8/thread) --------
template <bool TA, bool TB>
__global__ void __launch_bounds__(256) gemm_kernel(
        const float* __restrict__ A, const float* __restrict__ B,
        float* __restrict__ C,
        int M, int N, int K, int lda, int ldb, int ldc,
        long long sA, long long sB, long long sC) {
    __shared__ float As[2][8][128];
    __shared__ float Bs[2][8][128];
    A += (long long)blockIdx.z * sA;
    B += (long long)blockIdx.z * sB;
    C += (long long)blockIdx.z * sC;
    int m0 = blockIdx.y * 128;
    int n0 = blockIdx.x * 128;
    int tid = threadIdx.x;
    int tx = tid & 15, ty = tid >> 4;

    float acc[8][8];
    #pragma unroll
    for (int i = 0; i < 8; i++)
        #pragma unroll
        for (int j = 0; j < 8; j++) acc[i][j] = 0.f;

    float pa[4], pb[4];

    auto loadA = [&](int k0) {
        #pragma unroll
        for (int i = 0; i < 4; i++) {
            int idx = tid + i * 256;
            int mm, kk;
            if (TA) { mm = idx & 127; kk = idx >> 7; }
            else    { kk = idx & 7;   mm = idx >> 3; }
            int m = m0 + mm, k = k0 + kk;
            pa[i] = (m < M && k < K)
                      ? (TA ? A[(long long)k * lda + m] : A[(long long)m * lda + k])
                      : 0.f;
        }
    };
    auto stA = [&](int buf) {
        #pragma unroll
        for (int i = 0; i < 4; i++) {
            int idx = tid + i * 256;
            int mm, kk;
            if (TA) { mm = idx & 127; kk = idx >> 7; }
            else    { kk = idx & 7;   mm = idx >> 3; }
            As[buf][kk][mm] = pa[i];
        }
    };
    auto loadB = [&](int k0) {
        #pragma unroll
        for (int i = 0; i < 4; i++) {
            int idx = tid + i * 256;
            int nn, kk;
            if (TB) { kk = idx & 7;   nn = idx >> 3; }
            else    { nn = idx & 127; kk = idx >> 7; }
            int n = n0 + nn, k = k0 + kk;
            pb[i] = (n < N && k < K)
                      ? (TB ? B[(long long)n * ldb + k] : B[(long long)k * ldb + n])
                      : 0.f;
        }
    };
    auto stB = [&](int buf) {
        #pragma unroll
        for (int i = 0; i < 4; i++) {
            int idx = tid + i * 256;
            int nn, kk;
            if (TB) { kk = idx & 7;   nn = idx >> 3; }
            else    { nn = idx & 127; kk = idx >> 7; }
            Bs[buf][kk][nn] = pb[i];
        }
    };
    auto compute = [&](int buf) {
        #pragma unroll
        for (int kk = 0; kk < 8; kk++) {
            float4 a0 = *reinterpret_cast<const float4*>(&As[buf][kk][ty * 8]);
            float4 a1 = *reinterpret_cast<const float4*>(&As[buf][kk][ty * 8 + 4]);
            float4 b0 = *reinterpret_cast<const float4*>(&Bs[buf][kk][tx * 8]);
            float4 b1 = *reinterpret_cast<const float4*>(&Bs[buf][kk][tx * 8 + 4]);
            float ra[8] = {a0.x, a0.y, a0.z, a0.w, a1.x, a1.y, a1.z, a1.w};
            float rb[8] = {b0.x, b0.y, b0.z, b0.w, b1.x, b1.y, b1.z, b1.w};
            #pragma unroll
            for (int i = 0; i < 8; i++)
                #pragma unroll
                for (int j = 0; j < 8; j++) acc[i][j] += ra[i] * rb[j];
        }
    };

    loadA(0); loadB(0);
    stA(0); stB(0);
    __syncthreads();
    int buf = 0;
    for (int k0 = 8; k0 < K; k0 += 8) {
        loadA(k0); loadB(k0);
        compute(buf);
        stA(buf ^ 1); stB(buf ^ 1);
        __syncthreads();
        buf ^= 1;
    }
    compute(buf);

    #pragma unroll
    for (int i = 0; i < 8; i++) {
        int m = m0 + ty * 8 + i;
        if (m >= M) continue;
        #pragma unroll
        for (int j = 0; j < 8; j++) {
            int n = n0 + tx * 8 + j;
            if (n < N) C[(long long)m * ldc + n] = acc[i][j];
        }
    }
}

// ---------------- elementwise / reduction kernels ----------------
// euclid_to_lorentz: rows 256 -> 257
__global__ void k_e2l(const float* __restrict__ in, float* __restrict__ out) {
    __shared__ float sred[33];
    long long row = blockIdx.x;
    int t = threadIdx.x;
    float x = in[row * 256 + t];
    float ssq = blockReduceSum(x * x, sred);
    float xn = sqrtf(fmaxf(ssq, 1e-15f)) + 1e-5f;
    float sc = fminf(1.f, 2.0f / xn);
    x *= sc;
    float vn = sqrtf(fmaxf(ssq * sc * sc, 1e-15f));
    out[row * 257 + 1 + t] = sinhf(vn) / vn * x;
    if (t == 0) out[row * 257] = coshf(vn);
}

// lorentz_linear fix: raw space (256) + bias -> [time, space] (257)
__global__ void k_lfix(const float* __restrict__ raw, const float* __restrict__ b,
                       float* __restrict__ out) {
    __shared__ float sred[33];
    long long row = blockIdx.x;
    int t = threadIdx.x;
    float sp = raw[row * 256 + t] + b[1 + t];
    float ssq = blockReduceSum(sp * sp, sred);
    out[row * 257 + 1 + t] = sp;
    if (t == 0) out[row * 257] = sqrtf(ssq + 1.f);
}

// lorentz_to_poincare(lorentz_linear): raw space (128) + bias -> space/(time+1)
__global__ void k_pfix(float* __restrict__ buf, const float* __restrict__ b) {
    __shared__ float sred[33];
    long long row = blockIdx.x;
    int t = threadIdx.x;
    float sp = buf[row * 128 + t] + b[1 + t];
    float ssq = blockReduceSum(sp * sp, sred);
    buf[row * 128 + t] = sp / (sqrtf(ssq + 1.f) + 1.f);
}

// lorentz_act on rows of 1024 (in place) + row norm xnl
__global__ void k_act(float* __restrict__ lbig, float* __restrict__ xnl) {
    __shared__ float sred[33];
    long long row = blockIdx.x;
    int t = threadIdx.x;
    float g[4];
    float ss = 0.f;
    #pragma unroll
    for (int j = 0; j < 4; j++) {
        int m = t + j * 256;
        float v = lbig[row * 1024 + m];
        float gg = gelu_exact(v);
        if (m == 0) gg = 0.f;
        g[j] = gg;
        ss += gg * gg;
    }
    float ssq = blockReduceSum(ss, sred);
    float time = sqrtf(1.f + ssq);
    #pragma unroll
    for (int j = 0; j < 4; j++) {
        int m = t + j * 256;
        lbig[row * 1024 + m] = (m == 0) ? time : g[j];
    }
    if (t == 0) xnl[row] = sqrtf(fmaxf(time * time + ssq, 1e-15f));
}

// column norms of L_act
__global__ void k_colnorm(const float* __restrict__ lbig, float* __restrict__ xnc) {
    int b = blockIdx.y;
    int m = blockIdx.x * 256 + threadIdx.x;
    const float* base = lbig + (long long)b * 1024 * 1024 + m;
    float ss = 0.f;
    for (int n = 0; n < 1024; n++) {
        float v = base[(long long)n * 1024];
        ss += v * v;
    }
    xnc[b * 1024 + m] = sqrtf(fmaxf(ss, 1e-15f));
}

// Hs pipeline
__global__ void k_hs(float* __restrict__ ms, const float* __restrict__ hsa,
                     const float* __restrict__ xnl, const float* __restrict__ whs,
                     float* __restrict__ lgs) {
    __shared__ float sred[102];
    long long row = blockIdx.x;
    int t = threadIdx.x;
    float v = ms[row * 128 + t];
    float mxn = sqrtf(fmaxf(blockReduceSum(v * v, sred), 1e-15f));
    float xn = xnl[row];
    float fac = tanhf(mxn / xn * artanh_clip(xn)) / mxn;
    float y = fac * v;
    float x = hsa[row * 128 + t];
    float xy = x * y, x2 = x * x, y2 = y * y;
    blockReduceSum3(xy, x2, y2, sred);
    float den = fmaxf(1.f + 2.f * xy + x2 * y2, 1e-15f);
    float h = ((1.f + 2.f * xy + y2) * x + (1.f - x2) * y) / den;
    float hn = sqrtf(fmaxf(blockReduceSum(h * h, sred), 1e-15f));
    float u = artanh_clip(hn) / hn * h;
    float g = gelu_exact(u);
    float un = sqrtf(fmaxf(blockReduceSum(g * g, sred), 1e-15f));
    float o = tanhf(un) / un * g;
    ms[row * 128 + t] = o;
    float dot = o * whs[t], on2 = o * o, dummy = 0.f;
    blockReduceSum3(dot, on2, dummy, sred);
    if (t == 0) {
        float on = sqrtf(fmaxf(on2, 1e-15f));
        float mx1 = sqrtf(fmaxf(dot * dot, 1e-15f));
        lgs[row] = tanhf(mx1 / on * artanh_clip(on)) * (dot / mx1);
    }
}

// mobius_matvec factor for Hc_b (in place on mc)
__global__ void k_hcfac(float* __restrict__ mc, const float* __restrict__ xnc) {
    __shared__ float sred[33];
    long long row = blockIdx.x;
    int t = threadIdx.x;
    float v = mc[row * 128 + t];
    float mxn = sqrtf(fmaxf(blockReduceSum(v * v, sred), 1e-15f));
    float xn = xnc[row];
    float fac = tanhf(mxn / xn * artanh_clip(xn)) / mxn;
    mc[row * 128 + t] = fac * v;
}

// Hc pipeline over rows of 1024 (the m axis), writes Hc as (b,k,m)
__global__ void k_hc(const float* __restrict__ hca, const float* __restrict__ mc,
                     float* __restrict__ hct) {
    __shared__ float sred[102];
    int b = blockIdx.y, kq = blockIdx.x;
    int t = threadIdx.x;
    float x[4], y[4];
    #pragma unroll
    for (int j = 0; j < 4; j++) {
        int m = t + j * 256;
        long long idx = ((long long)b * 1024 + m) * 128 + kq;
        x[j] = hca[idx];
        y[j] = mc[idx];
    }
    float pxy = 0.f, px2 = 0.f, py2 = 0.f;
    #pragma unroll
    for (int j = 0; j < 4; j++) { pxy += x[j] * y[j]; px2 += x[j] * x[j]; py2 += y[j] * y[j]; }
    blockReduceSum3(pxy, px2, py2, sred);
    float xy = pxy, x2 = px2, y2 = py2;
    float den = fmaxf(1.f + 2.f * xy + x2 * y2, 1e-15f);
    float h[4];
    float hs = 0.f;
    #pragma unroll
    for (int j = 0; j < 4; j++) {
        h[j] = ((1.f + 2.f * xy + y2) * x[j] + (1.f - x2) * y[j]) / den;
        hs += h[j] * h[j];
    }
    float hn = sqrtf(fmaxf(blockReduceSum(hs, sred), 1e-15f));
    float fa = artanh_clip(hn) / hn;
    float g[4];
    float gs = 0.f;
    #pragma unroll
    for (int j = 0; j < 4; j++) { g[j] = gelu_exact(fa * h[j]); gs += g[j] * g[j]; }
    float un = sqrtf(fmaxf(blockReduceSum(gs, sred), 1e-15f));
    float fb = tanhf(un) / un;
    #pragma unroll
    for (int j = 0; j < 4; j++) {
        int m = t + j * 256;
        hct[((long long)b * 128 + kq) * 1024 + m] = fb * g[j];
    }
}

// Ac logits
__global__ void k_logc(const float* __restrict__ hct, const float* __restrict__ whc,
                       float* __restrict__ lgc) {
    int b = blockIdx.y;
    int m = blockIdx.x * 256 + threadIdx.x;
    const float* base = hct + (long long)b * 128 * 1024 + m;
    float ss = 0.f, dot = 0.f;
    #pragma unroll 4
    for (int k = 0; k < 128; k++) {
        float v = base[(long long)k * 1024];
        ss += v * v;
        dot += v * whc[k];
    }
    float xn = sqrtf(fmaxf(ss, 1e-15f));
    float mxn = sqrtf(fmaxf(dot * dot, 1e-15f));
    lgc[b * 1024 + m] = tanhf(mxn / xn * artanh_clip(xn)) * (dot / mxn);
}

__global__ void k_softmax(const float* __restrict__ in, float* __restrict__ out) {
    __shared__ float sred[33];
    int b = blockIdx.x, t = threadIdx.x;
    float v[4];
    float mx = -3.4e38f;
    #pragma unroll
    for (int j = 0; j < 4; j++) {
        v[j] = in[b * 1024 + t + j * 256];
        mx = fmaxf(mx, v[j]);
    }
    mx = blockReduceMax(mx, sred);
    float s = 0.f;
    #pragma unroll
    for (int j = 0; j < 4; j++) { v[j] = expf(v[j] - mx); s += v[j]; }
    s = blockReduceSum(s, sred);
    #pragma unroll
    for (int j = 0; j < 4; j++) out[b * 1024 + t + j * 256] = v[j] / s;
}

// centroid + lorentz_concat -> co_sc (32,513)
__global__ void k_final(const float* __restrict__ ls, const float* __restrict__ lc,
                        const float* __restrict__ as_, const float* __restrict__ ac_,
                        float* __restrict__ out) {
    __shared__ float sred[33];
    __shared__ float wsm[1024];
    __shared__ float avg[257];
    __shared__ float z[512];
    int b = blockIdx.x, t = threadIdx.x;

    #pragma unroll
    for (int j = 0; j < 4; j++) wsm[t + j * 256] = as_[b * 1024 + t + j * 256];
    __syncthreads();
    float acc = 0.f, acc2 = 0.f;
    const float* lsb = ls + (long long)b * 1024 * 257;
    for (int n = 0; n < 1024; n++) {
        float w = wsm[n];
        acc += w * lsb[n * 257 + t];
        if (t == 0) acc2 += w * lsb[n * 257 + 256];
    }
    avg[t] = acc;
    if (t == 0) avg[256] = acc2;
    __syncthreads();
    float spsum = blockReduceSum(avg[1 + t] * avg[1 + t], sred);
    float a0 = avg[0];
    float den = sqrtf(fmaxf(fabsf(-a0 * a0 + spsum), 1e-8f));
    float cs = avg[1 + t] / den;
    float c0 = a0 / den;
    float spn = sqrtf(fmaxf(blockReduceSum(cs * cs, sred), 1e-15f));
    float tt = fmaxf(c0, 1.f + 1e-7f);
    z[t] = acoshf(tt) * cs / spn;
    __syncthreads();

    #pragma unroll
    for (int j = 0; j < 4; j++) wsm[t + j * 256] = ac_[b * 1024 + t + j * 256];
    __syncthreads();
    acc = 0.f; acc2 = 0.f;
    const float* lcb = lc + (long long)b * 1024 * 257;
    for (int n = 0; n < 1024; n++) {
        float w = wsm[n];
        acc += w * lcb[n * 257 + t];
        if (t == 0) acc2 += w * lcb[n * 257 + 256];
    }
    avg[t] = acc;
    if (t == 0) avg[256] = acc2;
    __syncthreads();
    spsum = blockReduceSum(avg[1 + t] * avg[1 + t], sred);
    a0 = avg[0];
    den = sqrtf(fmaxf(fabsf(-a0 * a0 + spsum), 1e-8f));
    cs = avg[1 + t] / den;
    c0 = a0 / den;
    spn = sqrtf(fmaxf(blockReduceSum(cs * cs, sred), 1e-15f));
    tt = fmaxf(c0, 1.f + 1e-7f);
    z[256 + t] = acoshf(tt) * cs / spn;
    __syncthreads();

    float zz = z[t] * z[t] + z[256 + t] * z[256 + t];
    float vn = sqrtf(fmaxf(blockReduceSum(zz, sred), 1e-15f));
    float f = sinhf(vn) / vn;
    float* ob = out + (long long)b * 513;
    if (t == 0) ob[0] = coshf(vn);
    ob[1 + t] = f * z[t];
    ob[257 + t] = f * z[256 + t];
}

// ---------------- host-side launch helpers ----------------
static void gemm(const float* A, const float* B, float* C, int M, int N, int K,
                 int lda, int ldb, int ldc, long long sA, long long sB, long long sC,
                 int batch, bool ta, bool tb) {
    dim3 grid((N + 127) / 128, (M + 127) / 128, batch);
    if (!ta && !tb) gemm_kernel<false, false><<<grid, 256>>>(A, B, C, M, N, K, lda, ldb, ldc, sA, sB, sC);
    else if (!ta && tb) gemm_kernel<false, true><<<grid, 256>>>(A, B, C, M, N, K, lda, ldb, ldc, sA, sB, sC);
    else if (ta && !tb) gemm_kernel<true, false><<<grid, 256>>>(A, B, C, M, N, K, lda, ldb, ldc, sA, sB, sC);
    else gemm_kernel<true, true><<<grid, 256>>>(A, B, C, M, N, K, lda, ldb, ldc, sA, sB, sC);
}

extern "C" void kernel_launch(void* const* d_in, const int* in_sizes, int n_in,
                              void* d_out, int out_size) {
    const float* sent = (const float*)d_in[0];
    const float* comm = (const float*)d_in[1];
    const float* WlW  = (const float*)d_in[2];
    const float* Wlb  = (const float*)d_in[3];
    const float* WcW  = (const float*)d_in[4];
    const float* Wcb  = (const float*)d_in[5];
    const float* WsW  = (const float*)d_in[6];
    const float* Wsb  = (const float*)d_in[7];
    const float* whs  = (const float*)d_in[8];
    const float* whc  = (const float*)d_in[9];
    float* out = (float*)d_out;

    float* S = nullptr;
    cudaGetSymbolAddress((void**)&S, g_scratch);

    float* yre  = S + OFF_YRE;
    float* yim  = S + OFF_YIM;
    float* zf   = S + OFF_ZF;
    float* sfft = S + OFF_SFFT;
    float* cfft = S + OFF_CFFT;
    float* Ls   = S + OFF_LS;
    float* Lc   = S + OFF_LC;
    float* lraw = S + OFF_LRAW;
    float* lfix = S + OFF_LFIX;
    float* lbig = S + OFF_LBIG;
    float* xnl  = S + OFF_XNL;
    float* xnc  = S + OFF_XNC;
    float* hsa  = S + OFF_HSA;
    float* hca  = S + OFF_HCA;
    float* ms   = S + OFF_MS;
    float* mc   = S + OFF_MC;
    float* hct  = S + OFF_HCT;
    float* lgs  = S + OFF_LGS;
    float* lgc  = S + OFF_LGC;

    float* out_co = out;                 // (32,513)
    float* out_as = out + 32 * 513;      // (32,1024)
    float* out_ac = out_as + 32 * 1024;  // (32,1024)

    // ---- FFT (real part of fft2) via Stockham FFTs ----
    // sentence
    f_row256<false><<<32 * 1024, 128>>>(sent, yre, yim);
    f_col1024<<<dim3(129, 32), 512>>>(yre, yim, zf);
    f_mirror<<<dim3(127, 32), 256>>>(zf);
    f_transpose<<<dim3(32, 8, 32), dim3(32, 8)>>>(zf, sfft);
    k_e2l<<<32 * 1024, 256>>>(sfft, Ls);
    // comment (p_logmap0 fused into row FFT)
    f_row256<true><<<32 * 1024, 128>>>(comm, yre, yim);
    f_col1024<<<dim3(129, 32), 512>>>(yre, yim, zf);
    f_mirror<<<dim3(127, 32), 256>>>(zf);
    f_transpose<<<dim3(32, 8, 32), dim3(32, 8)>>>(zf, cfft);
    k_e2l<<<32 * 1024, 256>>>(cfft, Lc);

    // lorentz_linear(Lc, Wl) -> lfix (space only GEMM, skip output row 0 of W)
    gemm(Lc, WlW + 257, lraw, 32 * 1024, 256, 257, 257, 257, 256, 0, 0, 0, 1, false, true);
    k_lfix<<<32 * 1024, 256>>>(lraw, Wlb, lfix);

    // einsum('bnd,bmd->bnm', Ls, lfix)
    gemm(Ls, lfix, lbig, 1024, 1024, 257, 257, 257, 1024, 1024LL * 257, 1024LL * 257, 1024LL * 1024, 32, false, true);
    k_act<<<32 * 1024, 256>>>(lbig, xnl);
    k_colnorm<<<dim3(4, 32), 256>>>(lbig, xnc);

    // Hs_a, Hc_a (poincare of lorentz_linear)
    gemm(Ls, WsW + 257, hsa, 32 * 1024, 128, 257, 257, 257, 128, 0, 0, 0, 1, false, true);
    k_pfix<<<32 * 1024, 128>>>(hsa, Wsb);
    gemm(Lc, WcW + 257, hca, 32 * 1024, 128, 257, 257, 257, 128, 0, 0, 0, 1, false, true);
    k_pfix<<<32 * 1024, 128>>>(hca, Wcb);

    // Hs path
    gemm(lbig, hca, ms, 1024, 128, 1024, 1024, 128, 128, 1024LL * 1024, 1024LL * 128, 1024LL * 128, 32, false, false);
    k_hs<<<32 * 1024, 128>>>(ms, hsa, xnl, whs, lgs);
    k_softmax<<<32, 256>>>(lgs, out_as);

    // Hc path
    gemm(lbig, hsa, mc, 1024, 128, 1024, 1024, 128, 128, 1024LL * 1024, 1024LL * 128, 1024LL * 128, 32, true, false);
    k_hcfac<<<32 * 1024, 128>>>(mc, xnc);
    k_hc<<<dim3(128, 32), 256>>>(hca, mc, hct);
    k_logc<<<dim3(4, 32), 256>>>(hct, whc, lgc);
    k_softmax<<<32, 256>>>(lgc, out_ac);

    // centroids + concat
    k_final<<<32, 256>>>(Ls, Lc, out_as, out_ac, out_co);

    (void)in_sizes; (void)n_in; (void)out_size;
}